// round 4
// baseline (speedup 1.0000x reference)
#include <cuda_runtime.h>
#include <math.h>

#define NPTS   16384
#define NB     16
#define NSLOT  32          // 16 source + 16 target clouds
#define KKP    16
#define OUT_DEF (NB*NPTS*3)   // 786432
#define OUT_KP  (NB*KKP*3)    // 768
#define BN_EPS 1e-5f

// Packed fp32x2 helpers (Blackwell sm_100+; pattern from ptx_helpers.cuh)
#define PACK_DUP(r, x)   asm("mov.b64 %0, {%1, %1};" : "=l"(r) : "f"(x))
#define PACK2(r, lo, hi) asm("mov.b64 %0, {%1, %2};" : "=l"(r) : "f"(lo), "f"(hi))
#define UNPACK2(lo, hi, v) asm("mov.b64 {%0, %1}, %2;" : "=f"(lo), "=f"(hi) : "l"(v))
#define FFMA2(d, a, b)   asm("fma.rn.f32x2 %0, %1, %2, %0;" : "+l"(d) : "l"(a), "l"(b))

typedef unsigned long long u64;

// ----------------------------------------------------------------------------
// Device scratch (no allocations allowed)
// ----------------------------------------------------------------------------
__device__ float g_w1f[64*3];
__device__ float g_b1f[64];
__device__ float g_w2t[64*128];     // transposed + BN-folded: [k][d]
__device__ float g_b2f[128];
__device__ float g_w3t[128*128];    // transposed + BN-folded: [k][d]
__device__ float g_b3f[128];
__device__ int   g_lat[NSLOT*128];  // latent max (float bits; relu => >=0)
__device__ float g_kp[NSLOT*48];    // MLP-predicted keypoints
__device__ float g_sel[NSLOT*48];   // FPS-selected keypoints
__device__ float g_cage[NB*1536];   // cage = grid + disp, [b][512][3]
__device__ float g_pmm[NB*6];       // per-batch min3,max3 of source points

// ----------------------------------------------------------------------------
// Prep: fold BN into weights (transposed layout), zero latents
// ----------------------------------------------------------------------------
__global__ void prep_kernel(
    const float* w1, const float* b1, const float* g1, const float* be1,
    const float* m1, const float* v1,
    const float* w2, const float* b2, const float* g2, const float* be2,
    const float* m2, const float* v2,
    const float* w3, const float* b3, const float* g3, const float* be3,
    const float* m3, const float* v3)
{
    int t = threadIdx.x;
    for (int d = t; d < 64; d += 256) {
        float s = g1[d] * rsqrtf(v1[d] + BN_EPS);
        g_w1f[d*3+0] = w1[d*3+0]*s;
        g_w1f[d*3+1] = w1[d*3+1]*s;
        g_w1f[d*3+2] = w1[d*3+2]*s;
        g_b1f[d] = (b1[d]-m1[d])*s + be1[d];
    }
    for (int d = t; d < 128; d += 256) {
        float s2 = g2[d] * rsqrtf(v2[d] + BN_EPS);
        for (int k = 0; k < 64; k++)  g_w2t[k*128+d] = w2[d*64+k]*s2;
        g_b2f[d] = (b2[d]-m2[d])*s2 + be2[d];
        float s3 = g3[d] * rsqrtf(v3[d] + BN_EPS);
        for (int k = 0; k < 128; k++) g_w3t[k*128+d] = w3[d*128+k]*s3;
        g_b3f[d] = (b3[d]-m3[d])*s3 + be3[d];
    }
    for (int i = t; i < NSLOT*128; i += 256) g_lat[i] = 0;   // 0 bits == 0.0f
}

// ----------------------------------------------------------------------------
// Encoder: 3->64->128->128 MLP + segmented max over N.
// Block: 256 threads (8 warps), 4 sub-tiles of 64 points.
// Layers 2/3 use packed fp32x2 FFMA: thread owns 4 point-PAIRS x 4 dims
// (16 f32x2 accumulators). Activations stored transposed [k][p] (stride 66
// floats: 8B-aligned for LDS.64, bank-spread for the transposed stores) so
// the point-pair operand is a single broadcast LDS.64; the per-dim weight is
// duplicated into both lanes with mov.b64 {w,w} (alu pipe, hides under fma).
// Arithmetic per element is bit-identical fp32 FMA in the same k-order.
// ----------------------------------------------------------------------------
#define ENC_TP   64
#define ENC_SUBT 4
#define HS 66   // transposed-activation row stride in floats (even, padded)
#define ENC_SMEM_FLOATS (64*128 + 128*128 + 64*HS + 128*HS + 64*3 + 8*128)
#define ENC_SMEM_BYTES  (ENC_SMEM_FLOATS*4)

extern __shared__ float enc_smem[];

__global__ __launch_bounds__(256, 1)
void enc_kernel(const float* __restrict__ src, const float* __restrict__ tgt)
{
    float* sW2t = enc_smem;                 // 64*128
    float* sW3t = sW2t + 64*128;            // 128*128
    float* sH1t = sW3t + 128*128;           // 64 k  x HS (points)
    float* sH2t = sH1t + 64*HS;             // 128 k x HS (points)
    float* sX   = sH2t + 128*HS;            // 64*3
    float* sMax = sX   + 64*3;              // 8*128

    const int t    = threadIdx.x;
    const int warp = t >> 5;
    const int lane = t & 31;
    const int pbase = warp * 8;             // 8 points per warp => 4 pairs
    const int dbase = lane * 4;             // 4 output dims per lane
    const int slot = blockIdx.y;

    const float* pts = (slot < 16) ? (src + (size_t)slot*NPTS*3)
                                   : (tgt + (size_t)(slot-16)*NPTS*3);

    for (int i = t; i < 64*128;  i += 256) sW2t[i] = g_w2t[i];
    for (int i = t; i < 128*128; i += 256) sW3t[i] = g_w3t[i];

    for (int st = 0; st < ENC_SUBT; st++) {
        const int p0 = (blockIdx.x * ENC_SUBT + st) * ENC_TP;
        __syncthreads();   // weights ready (st=0); prior readers of sX/sH done
        for (int i = t; i < ENC_TP*3; i += 256) sX[i] = pts[(size_t)p0*3 + i];
        __syncthreads();

        // Layer 1: 64 pts x 64 dims, dot-3 -> transposed store sH1t[d][p]
        for (int i = t; i < ENC_TP*64; i += 256) {
            int d = i & 63, p = i >> 6;
            float v = g_b1f[d]
                    + sX[p*3+0]*g_w1f[d*3+0]
                    + sX[p*3+1]*g_w1f[d*3+1]
                    + sX[p*3+2]*g_w1f[d*3+2];
            sH1t[d*HS + p] = fmaxf(v, 0.f);
        }
        __syncthreads();

        // Layer 2: out 128 dims, K=64, packed f32x2 over point pairs
        {
            u64 acc[4][4];
            {
                float4 bb = *(const float4*)(g_b2f + dbase);
                u64 b0,b1,b2,b3;
                PACK_DUP(b0, bb.x); PACK_DUP(b1, bb.y);
                PACK_DUP(b2, bb.z); PACK_DUP(b3, bb.w);
                #pragma unroll
                for (int j = 0; j < 4; j++) {
                    acc[j][0]=b0; acc[j][1]=b1; acc[j][2]=b2; acc[j][3]=b3;
                }
            }
            #pragma unroll 4
            for (int k = 0; k < 64; k++) {
                float4 w = *(const float4*)(sW2t + k*128 + dbase);
                u64 wd0,wd1,wd2,wd3;
                PACK_DUP(wd0, w.x); PACK_DUP(wd1, w.y);
                PACK_DUP(wd2, w.z); PACK_DUP(wd3, w.w);
                const u64* hp = (const u64*)(sH1t + k*HS + pbase);
                u64 h0 = hp[0], h1 = hp[1], h2 = hp[2], h3 = hp[3];
                FFMA2(acc[0][0], h0, wd0); FFMA2(acc[0][1], h0, wd1);
                FFMA2(acc[0][2], h0, wd2); FFMA2(acc[0][3], h0, wd3);
                FFMA2(acc[1][0], h1, wd0); FFMA2(acc[1][1], h1, wd1);
                FFMA2(acc[1][2], h1, wd2); FFMA2(acc[1][3], h1, wd3);
                FFMA2(acc[2][0], h2, wd0); FFMA2(acc[2][1], h2, wd1);
                FFMA2(acc[2][2], h2, wd2); FFMA2(acc[2][3], h2, wd3);
                FFMA2(acc[3][0], h3, wd0); FFMA2(acc[3][1], h3, wd1);
                FFMA2(acc[3][2], h3, wd2); FFMA2(acc[3][3], h3, wd3);
            }
            // relu + transposed store sH2t[d][p] (pairs already packed)
            #pragma unroll
            for (int j = 0; j < 4; j++) {
                #pragma unroll
                for (int d = 0; d < 4; d++) {
                    float lo, hi;
                    UNPACK2(lo, hi, acc[j][d]);
                    lo = fmaxf(lo, 0.f); hi = fmaxf(hi, 0.f);
                    u64 pk; PACK2(pk, lo, hi);
                    *(u64*)(sH2t + (dbase+d)*HS + pbase + 2*j) = pk;
                }
            }
        }
        __syncthreads();

        // Layer 3: out 128 dims, K=128, packed f32x2, fused max over 8 points
        {
            u64 acc[4][4];
            {
                float4 bb = *(const float4*)(g_b3f + dbase);
                u64 b0,b1,b2,b3;
                PACK_DUP(b0, bb.x); PACK_DUP(b1, bb.y);
                PACK_DUP(b2, bb.z); PACK_DUP(b3, bb.w);
                #pragma unroll
                for (int j = 0; j < 4; j++) {
                    acc[j][0]=b0; acc[j][1]=b1; acc[j][2]=b2; acc[j][3]=b3;
                }
            }
            #pragma unroll 4
            for (int k = 0; k < 128; k++) {
                float4 w = *(const float4*)(sW3t + k*128 + dbase);
                u64 wd0,wd1,wd2,wd3;
                PACK_DUP(wd0, w.x); PACK_DUP(wd1, w.y);
                PACK_DUP(wd2, w.z); PACK_DUP(wd3, w.w);
                const u64* hp = (const u64*)(sH2t + k*HS + pbase);
                u64 h0 = hp[0], h1 = hp[1], h2 = hp[2], h3 = hp[3];
                FFMA2(acc[0][0], h0, wd0); FFMA2(acc[0][1], h0, wd1);
                FFMA2(acc[0][2], h0, wd2); FFMA2(acc[0][3], h0, wd3);
                FFMA2(acc[1][0], h1, wd0); FFMA2(acc[1][1], h1, wd1);
                FFMA2(acc[1][2], h1, wd2); FFMA2(acc[1][3], h1, wd3);
                FFMA2(acc[2][0], h2, wd0); FFMA2(acc[2][1], h2, wd1);
                FFMA2(acc[2][2], h2, wd2); FFMA2(acc[2][3], h2, wd3);
                FFMA2(acc[3][0], h3, wd0); FFMA2(acc[3][1], h3, wd1);
                FFMA2(acc[3][2], h3, wd2); FFMA2(acc[3][3], h3, wd3);
            }
            #pragma unroll
            for (int d = 0; d < 4; d++) {
                float m = -1e30f;
                #pragma unroll
                for (int j = 0; j < 4; j++) {
                    float lo, hi;
                    UNPACK2(lo, hi, acc[j][d]);
                    m = fmaxf(m, fmaxf(lo, hi));
                }
                // relu(max) == max(relu) (monotone)
                sMax[warp*128 + dbase + d] = fmaxf(m, 0.f);
            }
        }
        __syncthreads();
        if (t < 128) {
            float v = sMax[t];
            #pragma unroll
            for (int w = 1; w < 8; w++) v = fmaxf(v, sMax[w*128 + t]);
            atomicMax(&g_lat[slot*128 + t], __float_as_int(v)); // v >= 0
        }
    }
}

// ----------------------------------------------------------------------------
// Keypoint MLP: lat[128] -> relu(128) -> 48
// ----------------------------------------------------------------------------
__global__ void kp_kernel(const float* __restrict__ kpw1, const float* __restrict__ kpb1,
                          const float* __restrict__ kpw2, const float* __restrict__ kpb2)
{
    __shared__ float latS[128];
    __shared__ float h[128];
    int slot = blockIdx.x, t = threadIdx.x;
    latS[t] = __int_as_float(g_lat[slot*128 + t]);
    __syncthreads();
    float a = kpb1[t];
    for (int k = 0; k < 128; k++) a = fmaf(latS[k], kpw1[t*128+k], a);
    h[t] = fmaxf(a, 0.f);
    __syncthreads();
    if (t < 48) {
        float o = kpb2[t];
        for (int k = 0; k < 128; k++) o = fmaf(h[k], kpw2[t*128+k], o);
        g_kp[slot*48 + t] = o;
    }
}

// ----------------------------------------------------------------------------
// FPS: per cloud, 16 iterative argmax selections (first = vs MLP keypoints)
// jnp.argmax first-occurrence tie-break preserved (prefer smaller index).
// ----------------------------------------------------------------------------
__global__ __launch_bounds__(1024)
void fps_kernel(const float* __restrict__ src, const float* __restrict__ tgt,
                float* __restrict__ out)
{
    const int slot = blockIdx.x, t = threadIdx.x;
    const float* pts = (slot < 16) ? (src + (size_t)slot*NPTS*3)
                                   : (tgt + (size_t)(slot-16)*NPTS*3);
    float* kout = (slot < 16) ? (out + OUT_DEF + slot*48)
                              : (out + OUT_DEF + OUT_KP + (slot-16)*48);

    __shared__ float skp[48];
    __shared__ float sredV[32];
    __shared__ int   sredI[32];
    __shared__ float selS[3];
    if (t < 48) skp[t] = g_kp[slot*48 + t];

    float px[16], py[16], pz[16], mind[16];
    #pragma unroll
    for (int i = 0; i < 16; i++) {
        int n = t + i*1024;
        px[i] = pts[n*3+0]; py[i] = pts[n*3+1]; pz[i] = pts[n*3+2];
    }
    __syncthreads();

    // d0 = min over 16 MLP keypoints
    #pragma unroll
    for (int i = 0; i < 16; i++) {
        float best = 1e30f;
        #pragma unroll
        for (int k = 0; k < 16; k++) {
            float dx = px[i]-skp[k*3+0], dy = py[i]-skp[k*3+1], dz = pz[i]-skp[k*3+2];
            best = fminf(best, dx*dx + dy*dy + dz*dz);
        }
        mind[i] = best;
    }

    for (int it = 0; it < 16; it++) {
        float bv = -1e30f; int bi = 0x7fffffff;
        #pragma unroll
        for (int i = 0; i < 16; i++) {
            if (mind[i] > bv) { bv = mind[i]; bi = t + i*1024; }  // ascending idx
        }
        #pragma unroll
        for (int o = 16; o > 0; o >>= 1) {
            float ov = __shfl_down_sync(0xffffffffu, bv, o);
            int   oi = __shfl_down_sync(0xffffffffu, bi, o);
            if (ov > bv || (ov == bv && oi < bi)) { bv = ov; bi = oi; }
        }
        if ((t & 31) == 0) { sredV[t>>5] = bv; sredI[t>>5] = bi; }
        __syncthreads();
        if (t < 32) {
            bv = sredV[t]; bi = sredI[t];
            #pragma unroll
            for (int o = 16; o > 0; o >>= 1) {
                float ov = __shfl_down_sync(0xffffffffu, bv, o);
                int   oi = __shfl_down_sync(0xffffffffu, bi, o);
                if (ov > bv || (ov == bv && oi < bi)) { bv = ov; bi = oi; }
            }
            if (t == 0) {
                float sx = pts[bi*3+0], sy = pts[bi*3+1], sz = pts[bi*3+2];
                selS[0] = sx; selS[1] = sy; selS[2] = sz;
                kout[it*3+0] = sx; kout[it*3+1] = sy; kout[it*3+2] = sz;
                g_sel[slot*48 + it*3+0] = sx;
                g_sel[slot*48 + it*3+1] = sy;
                g_sel[slot*48 + it*3+2] = sz;
            }
        }
        __syncthreads();
        float sx = selS[0], sy = selS[1], sz = selS[2];
        #pragma unroll
        for (int i = 0; i < 16; i++) {
            float dx = px[i]-sx, dy = py[i]-sy, dz = pz[i]-sz;
            float d = dx*dx + dy*dy + dz*dz;
            mind[i] = (it == 0) ? d : fminf(mind[i], d);  // it==0: REPLACE (ref)
        }
    }
}

// ----------------------------------------------------------------------------
// Cage MLP: diff[48] -> relu(128) -> 1536; build cage = grid + disp
// ----------------------------------------------------------------------------
__global__ void cage_kernel(const float* __restrict__ cgw1, const float* __restrict__ cgb1,
                            const float* __restrict__ cgw2, const float* __restrict__ cgb2)
{
    __shared__ float diff[48];
    __shared__ float h[128];
    int b = blockIdx.x, t = threadIdx.x;
    if (t < 48) diff[t] = g_sel[(16+b)*48 + t] - g_sel[b*48 + t];
    __syncthreads();
    float a = cgb1[t];
    for (int k = 0; k < 48; k++) a = fmaf(diff[k], cgw1[t*48+k], a);
    h[t] = fmaxf(a, 0.f);
    __syncthreads();
    for (int o = t; o < 1536; o += 128) {
        float acc = cgb2[o];
        for (int k = 0; k < 128; k++) acc = fmaf(h[k], cgw2[o*128+k], acc);
        int c = o % 3, cell = o / 3;
        int i = cell >> 6, j = (cell >> 3) & 7, kz = cell & 7;
        int li = (c == 0) ? i : (c == 1) ? j : kz;
        g_cage[b*1536 + o] = (float)li * (1.0f/7.0f) + acc;
    }
}

// ----------------------------------------------------------------------------
// Per-batch min/max of source points
// ----------------------------------------------------------------------------
__global__ __launch_bounds__(1024)
void pmm_kernel(const float* __restrict__ src)
{
    int b = blockIdx.x, t = threadIdx.x;
    const float* p = src + (size_t)b*NPTS*3;
    float mn0=1e30f, mn1=1e30f, mn2=1e30f, mx0=-1e30f, mx1=-1e30f, mx2=-1e30f;
    for (int n = t; n < NPTS; n += 1024) {
        float x = p[n*3+0], y = p[n*3+1], z = p[n*3+2];
        mn0 = fminf(mn0,x); mx0 = fmaxf(mx0,x);
        mn1 = fminf(mn1,y); mx1 = fmaxf(mx1,y);
        mn2 = fminf(mn2,z); mx2 = fmaxf(mx2,z);
    }
    #pragma unroll
    for (int o = 16; o > 0; o >>= 1) {
        mn0 = fminf(mn0, __shfl_down_sync(0xffffffffu, mn0, o));
        mn1 = fminf(mn1, __shfl_down_sync(0xffffffffu, mn1, o));
        mn2 = fminf(mn2, __shfl_down_sync(0xffffffffu, mn2, o));
        mx0 = fmaxf(mx0, __shfl_down_sync(0xffffffffu, mx0, o));
        mx1 = fmaxf(mx1, __shfl_down_sync(0xffffffffu, mx1, o));
        mx2 = fmaxf(mx2, __shfl_down_sync(0xffffffffu, mx2, o));
    }
    __shared__ float s[32][6];
    if ((t & 31) == 0) {
        s[t>>5][0]=mn0; s[t>>5][1]=mn1; s[t>>5][2]=mn2;
        s[t>>5][3]=mx0; s[t>>5][4]=mx1; s[t>>5][5]=mx2;
    }
    __syncthreads();
    if (t < 32) {
        mn0=s[t][0]; mn1=s[t][1]; mn2=s[t][2]; mx0=s[t][3]; mx1=s[t][4]; mx2=s[t][5];
        #pragma unroll
        for (int o = 16; o > 0; o >>= 1) {
            mn0 = fminf(mn0, __shfl_down_sync(0xffffffffu, mn0, o));
            mn1 = fminf(mn1, __shfl_down_sync(0xffffffffu, mn1, o));
            mn2 = fminf(mn2, __shfl_down_sync(0xffffffffu, mn2, o));
            mx0 = fmaxf(mx0, __shfl_down_sync(0xffffffffu, mx0, o));
            mx1 = fmaxf(mx1, __shfl_down_sync(0xffffffffu, mx1, o));
            mx2 = fmaxf(mx2, __shfl_down_sync(0xffffffffu, mx2, o));
        }
        if (t == 0) {
            g_pmm[b*6+0]=mn0; g_pmm[b*6+1]=mn1; g_pmm[b*6+2]=mn2;
            g_pmm[b*6+3]=mx0; g_pmm[b*6+4]=mx1; g_pmm[b*6+5]=mx2;
        }
    }
}

// ----------------------------------------------------------------------------
// Trilinear cage deform
// ----------------------------------------------------------------------------
__global__ void deform_kernel(const float* __restrict__ src, float* __restrict__ out)
{
    int b = blockIdx.y, t = threadIdx.x;
    __shared__ float cg[1536];
    __shared__ float pm[6];
    for (int i = t; i < 1536; i += 256) cg[i] = g_cage[b*1536 + i];
    if (t < 6) pm[t] = g_pmm[b*6 + t];
    __syncthreads();

    int n = blockIdx.x*256 + t;
    const float* p = src + ((size_t)b*NPTS + n)*3;
    float x = p[0], y = p[1], z = p[2];
    float tx = (x - pm[0]) / (pm[3]-pm[0] + 1e-6f) * 7.f;
    float ty = (y - pm[1]) / (pm[4]-pm[1] + 1e-6f) * 7.f;
    float tz = (z - pm[2]) / (pm[5]-pm[2] + 1e-6f) * 7.f;
    int u = min(max((int)tx, 0), 6);
    int v = min(max((int)ty, 0), 6);
    int w = min(max((int)tz, 0), 6);
    float wx = tx - (float)u, wy = ty - (float)v, wz = tz - (float)w;
    float ax = 1.f-wx, ay = 1.f-wy, az = 1.f-wz;

    int base = u*64 + v*8 + w;
    const float* c000 = &cg[(base     )*3];
    const float* c100 = &cg[(base + 64)*3];
    const float* c010 = &cg[(base +  8)*3];
    const float* c110 = &cg[(base + 72)*3];
    const float* c001 = &cg[(base +  1)*3];
    const float* c101 = &cg[(base + 65)*3];
    const float* c011 = &cg[(base +  9)*3];
    const float* c111 = &cg[(base + 73)*3];

    float w000 = ax*ay*az, w100 = wx*ay*az, w010 = ax*wy*az, w110 = wx*wy*az;
    float w001 = ax*ay*wz, w101 = wx*ay*wz, w011 = ax*wy*wz, w111 = wx*wy*wz;

    #pragma unroll
    for (int c = 0; c < 3; c++) {
        float d = w000*c000[c] + w100*c100[c] + w010*c010[c] + w110*c110[c]
                + w001*c001[c] + w101*c101[c] + w011*c011[c] + w111*c111[c];
        out[((size_t)b*NPTS + n)*3 + c] = p[c] + d;
    }
}

// ----------------------------------------------------------------------------
// Launch
// ----------------------------------------------------------------------------
extern "C" void kernel_launch(void* const* d_in, const int* in_sizes, int n_in,
                              void* d_out, int out_size)
{
    const float* src  = (const float*)d_in[0];
    const float* tgt  = (const float*)d_in[1];
    const float* ew1  = (const float*)d_in[2];
    const float* eb1  = (const float*)d_in[3];
    const float* g1   = (const float*)d_in[4];
    const float* be1  = (const float*)d_in[5];
    const float* m1   = (const float*)d_in[6];
    const float* v1   = (const float*)d_in[7];
    const float* ew2  = (const float*)d_in[8];
    const float* eb2  = (const float*)d_in[9];
    const float* g2   = (const float*)d_in[10];
    const float* be2  = (const float*)d_in[11];
    const float* m2   = (const float*)d_in[12];
    const float* v2   = (const float*)d_in[13];
    const float* ew3  = (const float*)d_in[14];
    const float* eb3  = (const float*)d_in[15];
    const float* g3   = (const float*)d_in[16];
    const float* be3  = (const float*)d_in[17];
    const float* m3   = (const float*)d_in[18];
    const float* v3   = (const float*)d_in[19];
    const float* kpw1 = (const float*)d_in[20];
    const float* kpb1 = (const float*)d_in[21];
    const float* kpw2 = (const float*)d_in[22];
    const float* kpb2 = (const float*)d_in[23];
    const float* cgw1 = (const float*)d_in[24];
    const float* cgb1 = (const float*)d_in[25];
    const float* cgw2 = (const float*)d_in[26];
    const float* cgb2 = (const float*)d_in[27];
    float* out = (float*)d_out;

    cudaFuncSetAttribute(enc_kernel, cudaFuncAttributeMaxDynamicSharedMemorySize,
                         ENC_SMEM_BYTES);

    prep_kernel<<<1, 256>>>(ew1, eb1, g1, be1, m1, v1,
                            ew2, eb2, g2, be2, m2, v2,
                            ew3, eb3, g3, be3, m3, v3);
    enc_kernel<<<dim3(NPTS/(ENC_TP*ENC_SUBT), NSLOT), 256, ENC_SMEM_BYTES>>>(src, tgt);
    kp_kernel<<<NSLOT, 128>>>(kpw1, kpb1, kpw2, kpb2);
    fps_kernel<<<NSLOT, 1024>>>(src, tgt, out);
    cage_kernel<<<NB, 128>>>(cgw1, cgb1, cgw2, cgb2);
    pmm_kernel<<<NB, 1024>>>(src);
    deform_kernel<<<dim3(NPTS/256, NB), 256>>>(src, out);
}

// round 6
// speedup vs baseline: 1.7424x; 1.7424x over previous
#include <cuda_runtime.h>
#include <math.h>

#define NPTS   16384
#define NB     16
#define NSLOT  32          // 16 source + 16 target clouds
#define KKP    16
#define OUT_DEF (NB*NPTS*3)   // 786432
#define OUT_KP  (NB*KKP*3)    // 768
#define BN_EPS 1e-5f

// ----------------------------------------------------------------------------
// Device scratch (no allocations allowed)
// ----------------------------------------------------------------------------
__device__ float g_w1f[64*3];
__device__ float g_b1f[64];
__device__ float g_w2t[64*128];     // transposed + BN-folded: [k][d]
__device__ float g_b2f[128];
__device__ float g_w3t[128*128];    // transposed + BN-folded: [k][d]
__device__ float g_b3f[128];
__device__ int   g_lat[NSLOT*128];  // latent max (float bits; relu => >=0)
__device__ float g_kp[NSLOT*48];    // MLP-predicted keypoints
__device__ float g_sel[NSLOT*48];   // FPS-selected keypoints
__device__ float g_cage[NB*1536];   // cage = grid + disp, [b][512][3]
__device__ float g_pmm[NB*6];       // per-batch min3,max3 of source points

// ----------------------------------------------------------------------------
// tf32 split + mma helpers
// x = hi + lo with hi = tf32(x) (low 13 mantissa bits cleared after round),
// lo = tf32(x - hi). 3 MMAs (hh + hl + lh) give ~2^-21 relative accuracy.
// ----------------------------------------------------------------------------
__device__ __forceinline__ void tf32_split(float x, unsigned &hi, unsigned &lo) {
    unsigned h; asm("cvt.rna.tf32.f32 %0, %1;" : "=r"(h) : "f"(x));
    float r = x - __uint_as_float(h);
    asm("cvt.rna.tf32.f32 %0, %1;" : "=r"(lo) : "f"(r));
    hi = h;
}

#define MMA_TF32(acc, A, Bv) \
    asm volatile("mma.sync.aligned.m16n8k8.row.col.f32.tf32.tf32.f32 " \
        "{%0,%1,%2,%3}, {%4,%5,%6,%7}, {%8,%9}, {%0,%1,%2,%3};" \
        : "+f"((acc)[0]), "+f"((acc)[1]), "+f"((acc)[2]), "+f"((acc)[3]) \
        : "r"((A)[0]), "r"((A)[1]), "r"((A)[2]), "r"((A)[3]), \
          "r"((Bv)[0]), "r"((Bv)[1]))

// ----------------------------------------------------------------------------
// Prep: fold BN into weights (transposed layout), zero latents
// ----------------------------------------------------------------------------
__global__ void prep_kernel(
    const float* w1, const float* b1, const float* g1, const float* be1,
    const float* m1, const float* v1,
    const float* w2, const float* b2, const float* g2, const float* be2,
    const float* m2, const float* v2,
    const float* w3, const float* b3, const float* g3, const float* be3,
    const float* m3, const float* v3)
{
    int t = threadIdx.x;
    for (int d = t; d < 64; d += 256) {
        float s = g1[d] * rsqrtf(v1[d] + BN_EPS);
        g_w1f[d*3+0] = w1[d*3+0]*s;
        g_w1f[d*3+1] = w1[d*3+1]*s;
        g_w1f[d*3+2] = w1[d*3+2]*s;
        g_b1f[d] = (b1[d]-m1[d])*s + be1[d];
    }
    for (int d = t; d < 128; d += 256) {
        float s2 = g2[d] * rsqrtf(v2[d] + BN_EPS);
        for (int k = 0; k < 64; k++)  g_w2t[k*128+d] = w2[d*64+k]*s2;
        g_b2f[d] = (b2[d]-m2[d])*s2 + be2[d];
        float s3 = g3[d] * rsqrtf(v3[d] + BN_EPS);
        for (int k = 0; k < 128; k++) g_w3t[k*128+d] = w3[d*128+k]*s3;
        g_b3f[d] = (b3[d]-m3[d])*s3 + be3[d];
    }
    for (int i = t; i < NSLOT*128; i += 256) g_lat[i] = 0;   // 0 bits == 0.0f
}

// ----------------------------------------------------------------------------
// Encoder: 3->64->128->128 MLP + segmented max over N.
// Layers 2/3 on tensor cores: mma.sync m16n8k8 tf32 with 3-term split
// (error ~1e-6, preserves all FPS argmax decisions => output matches fp32).
// Block: 256 threads (8 warps); subtile = 64 points.
// Warp (pgrp = w&1, nquad = w>>1) owns 32 pts x 32 dims:
//   2 m-tiles (16 rows) x 4 n-tiles (8 cols), K-loop in steps of 8.
// Fragment maps (PTX m16n8k8.tf32): g = lane>>2, tq = lane&3
//   A: a0=(g,tq) a1=(g+8,tq) a2=(g,tq+4) a3=(g+8,tq+4)      [row-major MxK]
//   B: b0=(k=tq, n=g) b1=(k=tq+4, n=g)                      [KxN]
//   D: c0=(g,2tq) c1=(g,2tq+1) c2=(g+8,2tq) c3=(g+8,2tq+1)
// Smem pads: HS1=68, HS2=132 (A-loads bank=4g+tq distinct),
//            WS=136 (B-loads bank=8tq+g distinct). 157 KB total, 1 CTA/SM.
// ----------------------------------------------------------------------------
#define ENC_TP   64
#define ENC_SUBT 8
#define HS1 68
#define HS2 132
#define WS  136
#define ENC_SMEM_FLOATS (64*WS + 128*WS + 64*HS1 + 64*HS2 + 192 + 256)
#define ENC_SMEM_BYTES  (ENC_SMEM_FLOATS*4)

extern __shared__ float enc_smem[];

__global__ __launch_bounds__(256, 1)
void enc_kernel(const float* __restrict__ src, const float* __restrict__ tgt)
{
    float* sW2  = enc_smem;                 // 64  x WS
    float* sW3  = sW2 + 64*WS;              // 128 x WS
    float* sH1  = sW3 + 128*WS;             // 64  x HS1
    float* sH2  = sH1 + 64*HS1;             // 64  x HS2
    float* sX   = sH2 + 64*HS2;             // 64*3
    float* sMax = sX  + 192;                // 2 x 128

    const int t     = threadIdx.x;
    const int warp  = t >> 5;
    const int lane  = t & 31;
    const int g     = lane >> 2;
    const int tq    = lane & 3;
    const int pgrp  = warp & 1;             // point half: rows 32*pgrp..+31
    const int nquad = warp >> 1;            // dim quad: cols 32*nquad..+31
    const int pbase = pgrp * 32;
    const int nb    = nquad * 32;
    const int slot  = blockIdx.y;

    const float* pts = (slot < 16) ? (src + (size_t)slot*NPTS*3)
                                   : (tgt + (size_t)(slot-16)*NPTS*3);

    // stage weights (padded stride WS)
    for (int i = t; i < 64*128;  i += 256) sW2[(i>>7)*WS + (i&127)] = g_w2t[i];
    for (int i = t; i < 128*128; i += 256) sW3[(i>>7)*WS + (i&127)] = g_w3t[i];

    // biases for this warp's 8-col n-tiles (hoisted; same every subtile)
    float bias2[4][2], bias3[4][2];
    #pragma unroll
    for (int nt = 0; nt < 4; nt++) {
        bias2[nt][0] = g_b2f[nb + nt*8 + 2*tq];
        bias2[nt][1] = g_b2f[nb + nt*8 + 2*tq + 1];
        bias3[nt][0] = g_b3f[nb + nt*8 + 2*tq];
        bias3[nt][1] = g_b3f[nb + nt*8 + 2*tq + 1];
    }

    for (int st = 0; st < ENC_SUBT; st++) {
        const int p0 = (blockIdx.x * ENC_SUBT + st) * ENC_TP;
        __syncthreads();   // weights ready (st=0); prior readers of sX/sH/sMax done
        for (int i = t; i < ENC_TP*3; i += 256) sX[i] = pts[(size_t)p0*3 + i];
        __syncthreads();

        // Layer 1 (scalar): 64 pts x 64 dims, dot-3
        for (int i = t; i < ENC_TP*64; i += 256) {
            int d = i & 63, p = i >> 6;
            float v = g_b1f[d]
                    + sX[p*3+0]*g_w1f[d*3+0]
                    + sX[p*3+1]*g_w1f[d*3+1]
                    + sX[p*3+2]*g_w1f[d*3+2];
            sH1[p*HS1 + d] = fmaxf(v, 0.f);
        }
        __syncthreads();

        // ---------------- Layer 2: D[64x128] = H1[64x64] @ W2, tensor ----
        {
            float acc[2][4][4];
            #pragma unroll
            for (int nt = 0; nt < 4; nt++)
                #pragma unroll
                for (int mg = 0; mg < 2; mg++) {
                    acc[mg][nt][0] = bias2[nt][0]; acc[mg][nt][1] = bias2[nt][1];
                    acc[mg][nt][2] = bias2[nt][0]; acc[mg][nt][3] = bias2[nt][1];
                }
            #pragma unroll 2
            for (int ks = 0; ks < 8; ks++) {
                const int k0 = ks*8;
                unsigned ah[2][4], al[2][4];
                #pragma unroll
                for (int mg = 0; mg < 2; mg++) {
                    const float* ab = sH1 + (pbase + mg*16 + g)*HS1 + k0 + tq;
                    tf32_split(ab[0],         ah[mg][0], al[mg][0]);
                    tf32_split(ab[8*HS1],     ah[mg][1], al[mg][1]);
                    tf32_split(ab[4],         ah[mg][2], al[mg][2]);
                    tf32_split(ab[8*HS1 + 4], ah[mg][3], al[mg][3]);
                }
                #pragma unroll
                for (int nt = 0; nt < 4; nt++) {
                    const float* wb = sW2 + (k0 + tq)*WS + nb + nt*8 + g;
                    unsigned bh[2], bl[2];
                    tf32_split(wb[0],    bh[0], bl[0]);
                    tf32_split(wb[4*WS], bh[1], bl[1]);
                    #pragma unroll
                    for (int mg = 0; mg < 2; mg++) {
                        MMA_TF32(acc[mg][nt], ah[mg], bh);
                        MMA_TF32(acc[mg][nt], ah[mg], bl);
                        MMA_TF32(acc[mg][nt], al[mg], bh);
                    }
                }
            }
            // relu + store H2 (float2: cols 2tq,2tq+1 contiguous, 8B aligned)
            #pragma unroll
            for (int mg = 0; mg < 2; mg++)
                #pragma unroll
                for (int nt = 0; nt < 4; nt++) {
                    int row0 = pbase + mg*16 + g;
                    int col  = nb + nt*8 + 2*tq;
                    float2 v0, v1;
                    v0.x = fmaxf(acc[mg][nt][0], 0.f);
                    v0.y = fmaxf(acc[mg][nt][1], 0.f);
                    v1.x = fmaxf(acc[mg][nt][2], 0.f);
                    v1.y = fmaxf(acc[mg][nt][3], 0.f);
                    *(float2*)(sH2 + row0*HS2 + col)     = v0;
                    *(float2*)(sH2 + (row0+8)*HS2 + col) = v1;
                }
        }
        __syncthreads();

        // ---------------- Layer 3: D[64x128] = H2[64x128] @ W3, + max ----
        {
            float acc[2][4][4];
            #pragma unroll
            for (int nt = 0; nt < 4; nt++)
                #pragma unroll
                for (int mg = 0; mg < 2; mg++) {
                    acc[mg][nt][0] = bias3[nt][0]; acc[mg][nt][1] = bias3[nt][1];
                    acc[mg][nt][2] = bias3[nt][0]; acc[mg][nt][3] = bias3[nt][1];
                }
            #pragma unroll 2
            for (int ks = 0; ks < 16; ks++) {
                const int k0 = ks*8;
                unsigned ah[2][4], al[2][4];
                #pragma unroll
                for (int mg = 0; mg < 2; mg++) {
                    const float* ab = sH2 + (pbase + mg*16 + g)*HS2 + k0 + tq;
                    tf32_split(ab[0],         ah[mg][0], al[mg][0]);
                    tf32_split(ab[8*HS2],     ah[mg][1], al[mg][1]);
                    tf32_split(ab[4],         ah[mg][2], al[mg][2]);
                    tf32_split(ab[8*HS2 + 4], ah[mg][3], al[mg][3]);
                }
                #pragma unroll
                for (int nt = 0; nt < 4; nt++) {
                    const float* wb = sW3 + (k0 + tq)*WS + nb + nt*8 + g;
                    unsigned bh[2], bl[2];
                    tf32_split(wb[0],    bh[0], bl[0]);
                    tf32_split(wb[4*WS], bh[1], bl[1]);
                    #pragma unroll
                    for (int mg = 0; mg < 2; mg++) {
                        MMA_TF32(acc[mg][nt], ah[mg], bh);
                        MMA_TF32(acc[mg][nt], ah[mg], bl);
                        MMA_TF32(acc[mg][nt], al[mg], bh);
                    }
                }
            }
            // max over this warp's 32 rows, then over row-groups via shfl
            #pragma unroll
            for (int nt = 0; nt < 4; nt++) {
                float m0 = fmaxf(fmaxf(acc[0][nt][0], acc[0][nt][2]),
                                 fmaxf(acc[1][nt][0], acc[1][nt][2]));
                float m1 = fmaxf(fmaxf(acc[0][nt][1], acc[0][nt][3]),
                                 fmaxf(acc[1][nt][1], acc[1][nt][3]));
                #pragma unroll
                for (int o = 4; o < 32; o <<= 1) {
                    m0 = fmaxf(m0, __shfl_xor_sync(0xffffffffu, m0, o));
                    m1 = fmaxf(m1, __shfl_xor_sync(0xffffffffu, m1, o));
                }
                if (g == 0) {   // relu(max) == max(relu) (monotone)
                    sMax[pgrp*128 + nb + nt*8 + 2*tq]     = fmaxf(m0, 0.f);
                    sMax[pgrp*128 + nb + nt*8 + 2*tq + 1] = fmaxf(m1, 0.f);
                }
            }
        }
        __syncthreads();
        if (t < 128) {
            float v = fmaxf(sMax[t], sMax[128 + t]);
            atomicMax(&g_lat[slot*128 + t], __float_as_int(v)); // v >= 0
        }
    }
}

// ----------------------------------------------------------------------------
// Keypoint MLP: lat[128] -> relu(128) -> 48
// ----------------------------------------------------------------------------
__global__ void kp_kernel(const float* __restrict__ kpw1, const float* __restrict__ kpb1,
                          const float* __restrict__ kpw2, const float* __restrict__ kpb2)
{
    __shared__ float latS[128];
    __shared__ float h[128];
    int slot = blockIdx.x, t = threadIdx.x;
    latS[t] = __int_as_float(g_lat[slot*128 + t]);
    __syncthreads();
    float a = kpb1[t];
    for (int k = 0; k < 128; k++) a = fmaf(latS[k], kpw1[t*128+k], a);
    h[t] = fmaxf(a, 0.f);
    __syncthreads();
    if (t < 48) {
        float o = kpb2[t];
        for (int k = 0; k < 128; k++) o = fmaf(h[k], kpw2[t*128+k], o);
        g_kp[slot*48 + t] = o;
    }
}

// ----------------------------------------------------------------------------
// FPS: per cloud, 16 iterative argmax selections (first = vs MLP keypoints)
// jnp.argmax first-occurrence tie-break preserved (prefer smaller index).
// ----------------------------------------------------------------------------
__global__ __launch_bounds__(1024)
void fps_kernel(const float* __restrict__ src, const float* __restrict__ tgt,
                float* __restrict__ out)
{
    const int slot = blockIdx.x, t = threadIdx.x;
    const float* pts = (slot < 16) ? (src + (size_t)slot*NPTS*3)
                                   : (tgt + (size_t)(slot-16)*NPTS*3);
    float* kout = (slot < 16) ? (out + OUT_DEF + slot*48)
                              : (out + OUT_DEF + OUT_KP + (slot-16)*48);

    __shared__ float skp[48];
    __shared__ float sredV[32];
    __shared__ int   sredI[32];
    __shared__ float selS[3];
    if (t < 48) skp[t] = g_kp[slot*48 + t];

    float px[16], py[16], pz[16], mind[16];
    #pragma unroll
    for (int i = 0; i < 16; i++) {
        int n = t + i*1024;
        px[i] = pts[n*3+0]; py[i] = pts[n*3+1]; pz[i] = pts[n*3+2];
    }
    __syncthreads();

    // d0 = min over 16 MLP keypoints
    #pragma unroll
    for (int i = 0; i < 16; i++) {
        float best = 1e30f;
        #pragma unroll
        for (int k = 0; k < 16; k++) {
            float dx = px[i]-skp[k*3+0], dy = py[i]-skp[k*3+1], dz = pz[i]-skp[k*3+2];
            best = fminf(best, dx*dx + dy*dy + dz*dz);
        }
        mind[i] = best;
    }

    for (int it = 0; it < 16; it++) {
        float bv = -1e30f; int bi = 0x7fffffff;
        #pragma unroll
        for (int i = 0; i < 16; i++) {
            if (mind[i] > bv) { bv = mind[i]; bi = t + i*1024; }  // ascending idx
        }
        #pragma unroll
        for (int o = 16; o > 0; o >>= 1) {
            float ov = __shfl_down_sync(0xffffffffu, bv, o);
            int   oi = __shfl_down_sync(0xffffffffu, bi, o);
            if (ov > bv || (ov == bv && oi < bi)) { bv = ov; bi = oi; }
        }
        if ((t & 31) == 0) { sredV[t>>5] = bv; sredI[t>>5] = bi; }
        __syncthreads();
        if (t < 32) {
            bv = sredV[t]; bi = sredI[t];
            #pragma unroll
            for (int o = 16; o > 0; o >>= 1) {
                float ov = __shfl_down_sync(0xffffffffu, bv, o);
                int   oi = __shfl_down_sync(0xffffffffu, bi, o);
                if (ov > bv || (ov == bv && oi < bi)) { bv = ov; bi = oi; }
            }
            if (t == 0) {
                float sx = pts[bi*3+0], sy = pts[bi*3+1], sz = pts[bi*3+2];
                selS[0] = sx; selS[1] = sy; selS[2] = sz;
                kout[it*3+0] = sx; kout[it*3+1] = sy; kout[it*3+2] = sz;
                g_sel[slot*48 + it*3+0] = sx;
                g_sel[slot*48 + it*3+1] = sy;
                g_sel[slot*48 + it*3+2] = sz;
            }
        }
        __syncthreads();
        float sx = selS[0], sy = selS[1], sz = selS[2];
        #pragma unroll
        for (int i = 0; i < 16; i++) {
            float dx = px[i]-sx, dy = py[i]-sy, dz = pz[i]-sz;
            float d = dx*dx + dy*dy + dz*dz;
            mind[i] = (it == 0) ? d : fminf(mind[i], d);  // it==0: REPLACE (ref)
        }
    }
}

// ----------------------------------------------------------------------------
// Cage MLP: diff[48] -> relu(128) -> 1536; build cage = grid + disp
// ----------------------------------------------------------------------------
__global__ void cage_kernel(const float* __restrict__ cgw1, const float* __restrict__ cgb1,
                            const float* __restrict__ cgw2, const float* __restrict__ cgb2)
{
    __shared__ float diff[48];
    __shared__ float h[128];
    int b = blockIdx.x, t = threadIdx.x;
    if (t < 48) diff[t] = g_sel[(16+b)*48 + t] - g_sel[b*48 + t];
    __syncthreads();
    float a = cgb1[t];
    for (int k = 0; k < 48; k++) a = fmaf(diff[k], cgw1[t*48+k], a);
    h[t] = fmaxf(a, 0.f);
    __syncthreads();
    for (int o = t; o < 1536; o += 128) {
        float acc = cgb2[o];
        for (int k = 0; k < 128; k++) acc = fmaf(h[k], cgw2[o*128+k], acc);
        int c = o % 3, cell = o / 3;
        int i = cell >> 6, j = (cell >> 3) & 7, kz = cell & 7;
        int li = (c == 0) ? i : (c == 1) ? j : kz;
        g_cage[b*1536 + o] = (float)li * (1.0f/7.0f) + acc;
    }
}

// ----------------------------------------------------------------------------
// Per-batch min/max of source points
// ----------------------------------------------------------------------------
__global__ __launch_bounds__(1024)
void pmm_kernel(const float* __restrict__ src)
{
    int b = blockIdx.x, t = threadIdx.x;
    const float* p = src + (size_t)b*NPTS*3;
    float mn0=1e30f, mn1=1e30f, mn2=1e30f, mx0=-1e30f, mx1=-1e30f, mx2=-1e30f;
    for (int n = t; n < NPTS; n += 1024) {
        float x = p[n*3+0], y = p[n*3+1], z = p[n*3+2];
        mn0 = fminf(mn0,x); mx0 = fmaxf(mx0,x);
        mn1 = fminf(mn1,y); mx1 = fmaxf(mx1,y);
        mn2 = fminf(mn2,z); mx2 = fmaxf(mx2,z);
    }
    #pragma unroll
    for (int o = 16; o > 0; o >>= 1) {
        mn0 = fminf(mn0, __shfl_down_sync(0xffffffffu, mn0, o));
        mn1 = fminf(mn1, __shfl_down_sync(0xffffffffu, mn1, o));
        mn2 = fminf(mn2, __shfl_down_sync(0xffffffffu, mn2, o));
        mx0 = fmaxf(mx0, __shfl_down_sync(0xffffffffu, mx0, o));
        mx1 = fmaxf(mx1, __shfl_down_sync(0xffffffffu, mx1, o));
        mx2 = fmaxf(mx2, __shfl_down_sync(0xffffffffu, mx2, o));
    }
    __shared__ float s[32][6];
    if ((t & 31) == 0) {
        s[t>>5][0]=mn0; s[t>>5][1]=mn1; s[t>>5][2]=mn2;
        s[t>>5][3]=mx0; s[t>>5][4]=mx1; s[t>>5][5]=mx2;
    }
    __syncthreads();
    if (t < 32) {
        mn0=s[t][0]; mn1=s[t][1]; mn2=s[t][2]; mx0=s[t][3]; mx1=s[t][4]; mx2=s[t][5];
        #pragma unroll
        for (int o = 16; o > 0; o >>= 1) {
            mn0 = fminf(mn0, __shfl_down_sync(0xffffffffu, mn0, o));
            mn1 = fminf(mn1, __shfl_down_sync(0xffffffffu, mn1, o));
            mn2 = fminf(mn2, __shfl_down_sync(0xffffffffu, mn2, o));
            mx0 = fmaxf(mx0, __shfl_down_sync(0xffffffffu, mx0, o));
            mx1 = fmaxf(mx1, __shfl_down_sync(0xffffffffu, mx1, o));
            mx2 = fmaxf(mx2, __shfl_down_sync(0xffffffffu, mx2, o));
        }
        if (t == 0) {
            g_pmm[b*6+0]=mn0; g_pmm[b*6+1]=mn1; g_pmm[b*6+2]=mn2;
            g_pmm[b*6+3]=mx0; g_pmm[b*6+4]=mx1; g_pmm[b*6+5]=mx2;
        }
    }
}

// ----------------------------------------------------------------------------
// Trilinear cage deform
// ----------------------------------------------------------------------------
__global__ void deform_kernel(const float* __restrict__ src, float* __restrict__ out)
{
    int b = blockIdx.y, t = threadIdx.x;
    __shared__ float cg[1536];
    __shared__ float pm[6];
    for (int i = t; i < 1536; i += 256) cg[i] = g_cage[b*1536 + i];
    if (t < 6) pm[t] = g_pmm[b*6 + t];
    __syncthreads();

    int n = blockIdx.x*256 + t;
    const float* p = src + ((size_t)b*NPTS + n)*3;
    float x = p[0], y = p[1], z = p[2];
    float tx = (x - pm[0]) / (pm[3]-pm[0] + 1e-6f) * 7.f;
    float ty = (y - pm[1]) / (pm[4]-pm[1] + 1e-6f) * 7.f;
    float tz = (z - pm[2]) / (pm[5]-pm[2] + 1e-6f) * 7.f;
    int u = min(max((int)tx, 0), 6);
    int v = min(max((int)ty, 0), 6);
    int w = min(max((int)tz, 0), 6);
    float wx = tx - (float)u, wy = ty - (float)v, wz = tz - (float)w;
    float ax = 1.f-wx, ay = 1.f-wy, az = 1.f-wz;

    int base = u*64 + v*8 + w;
    const float* c000 = &cg[(base     )*3];
    const float* c100 = &cg[(base + 64)*3];
    const float* c010 = &cg[(base +  8)*3];
    const float* c110 = &cg[(base + 72)*3];
    const float* c001 = &cg[(base +  1)*3];
    const float* c101 = &cg[(base + 65)*3];
    const float* c011 = &cg[(base +  9)*3];
    const float* c111 = &cg[(base + 73)*3];

    float w000 = ax*ay*az, w100 = wx*ay*az, w010 = ax*wy*az, w110 = wx*wy*az;
    float w001 = ax*ay*wz, w101 = wx*ay*wz, w011 = ax*wy*wz, w111 = wx*wy*wz;

    #pragma unroll
    for (int c = 0; c < 3; c++) {
        float d = w000*c000[c] + w100*c100[c] + w010*c010[c] + w110*c110[c]
                + w001*c001[c] + w101*c101[c] + w011*c011[c] + w111*c111[c];
        out[((size_t)b*NPTS + n)*3 + c] = p[c] + d;
    }
}

// ----------------------------------------------------------------------------
// Launch
// ----------------------------------------------------------------------------
extern "C" void kernel_launch(void* const* d_in, const int* in_sizes, int n_in,
                              void* d_out, int out_size)
{
    const float* src  = (const float*)d_in[0];
    const float* tgt  = (const float*)d_in[1];
    const float* ew1  = (const float*)d_in[2];
    const float* eb1  = (const float*)d_in[3];
    const float* g1   = (const float*)d_in[4];
    const float* be1  = (const float*)d_in[5];
    const float* m1   = (const float*)d_in[6];
    const float* v1   = (const float*)d_in[7];
    const float* ew2  = (const float*)d_in[8];
    const float* eb2  = (const float*)d_in[9];
    const float* g2   = (const float*)d_in[10];
    const float* be2  = (const float*)d_in[11];
    const float* m2   = (const float*)d_in[12];
    const float* v2   = (const float*)d_in[13];
    const float* ew3  = (const float*)d_in[14];
    const float* eb3  = (const float*)d_in[15];
    const float* g3   = (const float*)d_in[16];
    const float* be3  = (const float*)d_in[17];
    const float* m3   = (const float*)d_in[18];
    const float* v3   = (const float*)d_in[19];
    const float* kpw1 = (const float*)d_in[20];
    const float* kpb1 = (const float*)d_in[21];
    const float* kpw2 = (const float*)d_in[22];
    const float* kpb2 = (const float*)d_in[23];
    const float* cgw1 = (const float*)d_in[24];
    const float* cgb1 = (const float*)d_in[25];
    const float* cgw2 = (const float*)d_in[26];
    const float* cgb2 = (const float*)d_in[27];
    float* out = (float*)d_out;

    cudaFuncSetAttribute(enc_kernel, cudaFuncAttributeMaxDynamicSharedMemorySize,
                         ENC_SMEM_BYTES);

    prep_kernel<<<1, 256>>>(ew1, eb1, g1, be1, m1, v1,
                            ew2, eb2, g2, be2, m2, v2,
                            ew3, eb3, g3, be3, m3, v3);
    enc_kernel<<<dim3(NPTS/(ENC_TP*ENC_SUBT), NSLOT), 256, ENC_SMEM_BYTES>>>(src, tgt);
    kp_kernel<<<NSLOT, 128>>>(kpw1, kpb1, kpw2, kpb2);
    fps_kernel<<<NSLOT, 1024>>>(src, tgt, out);
    cage_kernel<<<NB, 128>>>(cgw1, cgb1, cgw2, cgb2);
    pmm_kernel<<<NB, 1024>>>(src);
    deform_kernel<<<dim3(NPTS/256, NB), 256>>>(src, out);
}

// round 8
// speedup vs baseline: 2.5369x; 1.4560x over previous
#include <cuda_runtime.h>
#include <cuda_bf16.h>
#include <math.h>
#include <cstdint>

#define NPTS   16384
#define NB     16
#define NSLOT  32          // 16 source + 16 target clouds
#define KKP    16
#define OUT_DEF (NB*NPTS*3)   // 786432
#define OUT_KP  (NB*KKP*3)    // 768
#define BN_EPS 1e-5f

// ----------------------------------------------------------------------------
// bf16 2-way split: v = h + m + r, |r| <= 2^-18 |v|
// ----------------------------------------------------------------------------
__device__ __forceinline__ void bsplit2(float v, unsigned short &h, unsigned short &m) {
    __nv_bfloat16 bh = __float2bfloat16(v);
    float r = v - __bfloat162float(bh);
    __nv_bfloat16 bm = __float2bfloat16(r);
    h = __bfloat16_as_ushort(bh);
    m = __bfloat16_as_ushort(bm);
}
__device__ __forceinline__ uint32_t pack_split_h(float v0, float v1) {
    unsigned short h0, m0, h1, m1;
    bsplit2(v0, h0, m0); bsplit2(v1, h1, m1);
    return (uint32_t)h0 | ((uint32_t)h1 << 16);
}
// returns both packed words
__device__ __forceinline__ void pack_split(float v0, float v1, uint32_t &ph, uint32_t &pm) {
    unsigned short h0, m0, h1, m1;
    bsplit2(v0, h0, m0); bsplit2(v1, h1, m1);
    ph = (uint32_t)h0 | ((uint32_t)h1 << 16);
    pm = (uint32_t)m0 | ((uint32_t)m1 << 16);
}

// bf16 m16n8k16 MMA, fp32 accumulate (baseline PTX, works on compute_103)
#define MMA_BF16(acc, A, B) \
    asm volatile("mma.sync.aligned.m16n8k16.row.col.f32.bf16.bf16.f32 " \
        "{%0,%1,%2,%3}, {%4,%5,%6,%7}, {%8,%9}, {%0,%1,%2,%3};" \
        : "+f"((acc)[0]), "+f"((acc)[1]), "+f"((acc)[2]), "+f"((acc)[3]) \
        : "r"((A)[0]), "r"((A)[1]), "r"((A)[2]), "r"((A)[3]), \
          "r"((B)[0]), "r"((B)[1]))

// ----------------------------------------------------------------------------
// Device scratch (no allocations allowed)
// ----------------------------------------------------------------------------
#define WS2 36   // W2 kpair stride (32 pairs + pad); banks 4g+tq conflict-free
#define WS3 68   // W3 kpair stride (64 pairs + pad)
#define HS1 36   // H1 kpair stride
#define HS2 68   // H2 kpair stride

__device__ float    g_w1f[64*3];
__device__ float    g_b1f[64];
__device__ uint32_t g_w2h[128*WS2];  // W2 split-hi, packed bf16x2 [n][kpair]
__device__ uint32_t g_w2m[128*WS2];  // W2 split-lo
__device__ float    g_b2f[128];
__device__ uint32_t g_w3h[128*WS3];
__device__ uint32_t g_w3m[128*WS3];
__device__ float    g_b3f[128];
__device__ int      g_lat[NSLOT*128];  // latent max (float bits; relu => >=0)
__device__ float    g_kp[NSLOT*48];
__device__ float    g_sel[NSLOT*48];
__device__ float    g_cage[NB*1536];
__device__ float    g_pmm[NB*6];

// ----------------------------------------------------------------------------
// Prep: fold BN into weights, 2-way bf16 split, pack k-pairs; zero latents
// ----------------------------------------------------------------------------
__global__ void prep_kernel(
    const float* w1, const float* b1, const float* g1, const float* be1,
    const float* m1, const float* v1,
    const float* w2, const float* b2, const float* g2, const float* be2,
    const float* m2, const float* v2,
    const float* w3, const float* b3, const float* g3, const float* be3,
    const float* m3, const float* v3)
{
    int t = threadIdx.x;
    for (int d = t; d < 64; d += 256) {
        float s = g1[d] * rsqrtf(v1[d] + BN_EPS);
        g_w1f[d*3+0] = w1[d*3+0]*s;
        g_w1f[d*3+1] = w1[d*3+1]*s;
        g_w1f[d*3+2] = w1[d*3+2]*s;
        g_b1f[d] = (b1[d]-m1[d])*s + be1[d];
    }
    for (int d = t; d < 128; d += 256) {
        float s2 = g2[d] * rsqrtf(v2[d] + BN_EPS);
        for (int k = 0; k < 64; k += 2) {
            uint32_t ph, pm;
            pack_split(w2[d*64+k]*s2, w2[d*64+k+1]*s2, ph, pm);
            g_w2h[d*WS2 + (k>>1)] = ph;
            g_w2m[d*WS2 + (k>>1)] = pm;
        }
        g_b2f[d] = (b2[d]-m2[d])*s2 + be2[d];
        float s3 = g3[d] * rsqrtf(v3[d] + BN_EPS);
        for (int k = 0; k < 128; k += 2) {
            uint32_t ph, pm;
            pack_split(w3[d*128+k]*s3, w3[d*128+k+1]*s3, ph, pm);
            g_w3h[d*WS3 + (k>>1)] = ph;
            g_w3m[d*WS3 + (k>>1)] = pm;
        }
        g_b3f[d] = (b3[d]-m3[d])*s3 + be3[d];
    }
    for (int i = t; i < NSLOT*128; i += 256) g_lat[i] = 0;
}

// ----------------------------------------------------------------------------
// Encoder: 3->64->128->128 MLP + segmented max, layers 2/3 on bf16 m16n8k16
// mma.sync with 2-way split (3 terms hh+hm+mh; dropped terms ~1e-5 rel —
// only affects 32 first-iteration FPS argmax decisions, all downstream exact).
// Block 256 threads (8 warps), subtile 64 pts. Warp (pgrp=w&1, nquad=w>>1)
// owns 32 pts x 32 dims: 2 m-tiles x 4 n-tiles, K in steps of 16 (8 kpairs).
// Fragments (m16n8k16, g=lane>>2, tq=lane&3), kpair-packed uint32 arrays:
//   A: a0=[row g][kp tq] a1=[g+8][tq] a2=[g][tq+4] a3=[g+8][tq+4]
//   B: b0=[n=g][kp tq]   b1=[n=g][kp tq+4]
//   D: c0=(g,2tq) c1=(g,2tq+1) c2=(g+8,2tq) c3=(g+8,2tq+1)
// All strides ≡ 4 (mod 32) => bank = 4g+tq, conflict-free.
// ----------------------------------------------------------------------------
#define ENC_TP   64
#define ENC_SUBT 8
#define ENC_SMEM_U32 (2*128*WS2 + 2*128*WS3 + 2*64*HS1 + 2*64*HS2 + 192 + 256)
#define ENC_SMEM_BYTES (ENC_SMEM_U32*4)

extern __shared__ uint32_t enc_smem[];

__global__ __launch_bounds__(256, 1)
void enc_kernel(const float* __restrict__ src, const float* __restrict__ tgt)
{
    uint32_t* sW2h = enc_smem;               // 128*WS2
    uint32_t* sW2m = sW2h + 128*WS2;
    uint32_t* sW3h = sW2m + 128*WS2;         // 128*WS3
    uint32_t* sW3m = sW3h + 128*WS3;
    uint32_t* sH1h = sW3m + 128*WS3;         // 64*HS1
    uint32_t* sH1m = sH1h + 64*HS1;
    uint32_t* sH2h = sH1m + 64*HS1;          // 64*HS2
    uint32_t* sH2m = sH2h + 64*HS2;
    float*    sX   = (float*)(sH2m + 64*HS2); // 192
    float*    sMax = sX + 192;                // 256

    const int t     = threadIdx.x;
    const int warp  = t >> 5;
    const int lane  = t & 31;
    const int g     = lane >> 2;
    const int tq    = lane & 3;
    const int pgrp  = warp & 1;
    const int nquad = warp >> 1;
    const int pbase = pgrp * 32;
    const int nb    = nquad * 32;
    const int slot  = blockIdx.y;

    const float* pts = (slot < 16) ? (src + (size_t)slot*NPTS*3)
                                   : (tgt + (size_t)(slot-16)*NPTS*3);

    // stage pre-split weights
    for (int i = t; i < 128*WS2; i += 256) { sW2h[i] = g_w2h[i]; sW2m[i] = g_w2m[i]; }
    for (int i = t; i < 128*WS3; i += 256) { sW3h[i] = g_w3h[i]; sW3m[i] = g_w3m[i]; }

    // per-thread biases for this warp's n-tiles (accumulator cols 2tq,2tq+1)
    float bias2[4][2], bias3[4][2];
    #pragma unroll
    for (int nt = 0; nt < 4; nt++) {
        bias2[nt][0] = g_b2f[nb + nt*8 + 2*tq];
        bias2[nt][1] = g_b2f[nb + nt*8 + 2*tq + 1];
        bias3[nt][0] = g_b3f[nb + nt*8 + 2*tq];
        bias3[nt][1] = g_b3f[nb + nt*8 + 2*tq + 1];
    }

    for (int st = 0; st < ENC_SUBT; st++) {
        const int p0 = (blockIdx.x * ENC_SUBT + st) * ENC_TP;
        __syncthreads();   // weights ready (st=0); prior readers of sX/sH done
        for (int i = t; i < ENC_TP*3; i += 256) sX[i] = pts[(size_t)p0*3 + i];
        __syncthreads();

        // Layer 1 (scalar): 64 pts x 32 d-pairs -> split -> packed H1
        for (int i = t; i < ENC_TP*32; i += 256) {
            int p = i >> 5, dp = i & 31;
            int d0 = 2*dp;
            float x = sX[p*3+0], y = sX[p*3+1], z = sX[p*3+2];
            float v0 = fmaxf(g_b1f[d0]   + x*g_w1f[d0*3+0] + y*g_w1f[d0*3+1] + z*g_w1f[d0*3+2], 0.f);
            float v1 = fmaxf(g_b1f[d0+1] + x*g_w1f[d0*3+3] + y*g_w1f[d0*3+4] + z*g_w1f[d0*3+5], 0.f);
            uint32_t ph, pm;
            pack_split(v0, v1, ph, pm);
            sH1h[p*HS1 + dp] = ph;
            sH1m[p*HS1 + dp] = pm;
        }
        __syncthreads();

        // ---------------- Layer 2: K=64 (4 k16 steps) ----------------
        {
            float acc[2][4][4];
            #pragma unroll
            for (int nt = 0; nt < 4; nt++)
                #pragma unroll
                for (int mg = 0; mg < 2; mg++) {
                    acc[mg][nt][0] = bias2[nt][0]; acc[mg][nt][1] = bias2[nt][1];
                    acc[mg][nt][2] = bias2[nt][0]; acc[mg][nt][3] = bias2[nt][1];
                }
            #pragma unroll
            for (int ks = 0; ks < 4; ks++) {
                const int kp0 = ks*8;
                uint32_t ah[2][4], am[2][4];
                #pragma unroll
                for (int mg = 0; mg < 2; mg++) {
                    const uint32_t* r0h = sH1h + (pbase + mg*16 + g)*HS1 + kp0;
                    const uint32_t* r0m = sH1m + (pbase + mg*16 + g)*HS1 + kp0;
                    ah[mg][0] = r0h[tq];            am[mg][0] = r0m[tq];
                    ah[mg][1] = r0h[8*HS1 + tq];    am[mg][1] = r0m[8*HS1 + tq];
                    ah[mg][2] = r0h[tq + 4];        am[mg][2] = r0m[tq + 4];
                    ah[mg][3] = r0h[8*HS1 + tq+4];  am[mg][3] = r0m[8*HS1 + tq+4];
                }
                #pragma unroll
                for (int nt = 0; nt < 4; nt++) {
                    const uint32_t* wh = sW2h + (nb + nt*8 + g)*WS2 + kp0;
                    const uint32_t* wm = sW2m + (nb + nt*8 + g)*WS2 + kp0;
                    uint32_t bh[2] = { wh[tq], wh[tq+4] };
                    uint32_t bm[2] = { wm[tq], wm[tq+4] };
                    #pragma unroll
                    for (int mg = 0; mg < 2; mg++) {
                        MMA_BF16(acc[mg][nt], ah[mg], bh);
                        MMA_BF16(acc[mg][nt], ah[mg], bm);
                        MMA_BF16(acc[mg][nt], am[mg], bh);
                    }
                }
            }
            // relu + split + packed store H2 (cols 2tq,2tq+1 form one pair)
            #pragma unroll
            for (int mg = 0; mg < 2; mg++)
                #pragma unroll
                for (int nt = 0; nt < 4; nt++) {
                    int row0 = pbase + mg*16 + g;
                    int cp   = (nb >> 1) + nt*4 + tq;    // column-pair index
                    uint32_t ph, pm;
                    pack_split(fmaxf(acc[mg][nt][0], 0.f), fmaxf(acc[mg][nt][1], 0.f), ph, pm);
                    sH2h[row0*HS2 + cp] = ph;
                    sH2m[row0*HS2 + cp] = pm;
                    pack_split(fmaxf(acc[mg][nt][2], 0.f), fmaxf(acc[mg][nt][3], 0.f), ph, pm);
                    sH2h[(row0+8)*HS2 + cp] = ph;
                    sH2m[(row0+8)*HS2 + cp] = pm;
                }
        }
        __syncthreads();

        // ---------------- Layer 3: K=128 (8 k16 steps) + fused max ----
        {
            float acc[2][4][4];
            #pragma unroll
            for (int nt = 0; nt < 4; nt++)
                #pragma unroll
                for (int mg = 0; mg < 2; mg++) {
                    acc[mg][nt][0] = bias3[nt][0]; acc[mg][nt][1] = bias3[nt][1];
                    acc[mg][nt][2] = bias3[nt][0]; acc[mg][nt][3] = bias3[nt][1];
                }
            #pragma unroll
            for (int ks = 0; ks < 8; ks++) {
                const int kp0 = ks*8;
                uint32_t ah[2][4], am[2][4];
                #pragma unroll
                for (int mg = 0; mg < 2; mg++) {
                    const uint32_t* r0h = sH2h + (pbase + mg*16 + g)*HS2 + kp0;
                    const uint32_t* r0m = sH2m + (pbase + mg*16 + g)*HS2 + kp0;
                    ah[mg][0] = r0h[tq];            am[mg][0] = r0m[tq];
                    ah[mg][1] = r0h[8*HS2 + tq];    am[mg][1] = r0m[8*HS2 + tq];
                    ah[mg][2] = r0h[tq + 4];        am[mg][2] = r0m[tq + 4];
                    ah[mg][3] = r0h[8*HS2 + tq+4];  am[mg][3] = r0m[8*HS2 + tq+4];
                }
                #pragma unroll
                for (int nt = 0; nt < 4; nt++) {
                    const uint32_t* wh = sW3h + (nb + nt*8 + g)*WS3 + kp0;
                    const uint32_t* wm = sW3m + (nb + nt*8 + g)*WS3 + kp0;
                    uint32_t bh[2] = { wh[tq], wh[tq+4] };
                    uint32_t bm[2] = { wm[tq], wm[tq+4] };
                    #pragma unroll
                    for (int mg = 0; mg < 2; mg++) {
                        MMA_BF16(acc[mg][nt], ah[mg], bh);
                        MMA_BF16(acc[mg][nt], ah[mg], bm);
                        MMA_BF16(acc[mg][nt], am[mg], bh);
                    }
                }
            }
            // max over this warp's 32 rows, then over row-groups via shfl
            #pragma unroll
            for (int nt = 0; nt < 4; nt++) {
                float m0 = fmaxf(fmaxf(acc[0][nt][0], acc[0][nt][2]),
                                 fmaxf(acc[1][nt][0], acc[1][nt][2]));
                float m1 = fmaxf(fmaxf(acc[0][nt][1], acc[0][nt][3]),
                                 fmaxf(acc[1][nt][1], acc[1][nt][3]));
                #pragma unroll
                for (int o = 4; o < 32; o <<= 1) {
                    m0 = fmaxf(m0, __shfl_xor_sync(0xffffffffu, m0, o));
                    m1 = fmaxf(m1, __shfl_xor_sync(0xffffffffu, m1, o));
                }
                if (g == 0) {   // relu(max) == max(relu) (monotone)
                    sMax[pgrp*128 + nb + nt*8 + 2*tq]     = fmaxf(m0, 0.f);
                    sMax[pgrp*128 + nb + nt*8 + 2*tq + 1] = fmaxf(m1, 0.f);
                }
            }
        }
        __syncthreads();
        if (t < 128) {
            float v = fmaxf(sMax[t], sMax[128 + t]);
            atomicMax(&g_lat[slot*128 + t], __float_as_int(v)); // v >= 0
        }
    }
}

// ----------------------------------------------------------------------------
// Keypoint MLP: lat[128] -> relu(128) -> 48
// ----------------------------------------------------------------------------
__global__ void kp_kernel(const float* __restrict__ kpw1, const float* __restrict__ kpb1,
                          const float* __restrict__ kpw2, const float* __restrict__ kpb2)
{
    __shared__ float latS[128];
    __shared__ float h[128];
    int slot = blockIdx.x, t = threadIdx.x;
    latS[t] = __int_as_float(g_lat[slot*128 + t]);
    __syncthreads();
    float a = kpb1[t];
    for (int k = 0; k < 128; k++) a = fmaf(latS[k], kpw1[t*128+k], a);
    h[t] = fmaxf(a, 0.f);
    __syncthreads();
    if (t < 48) {
        float o = kpb2[t];
        for (int k = 0; k < 128; k++) o = fmaf(h[k], kpw2[t*128+k], o);
        g_kp[slot*48 + t] = o;
    }
}

// ----------------------------------------------------------------------------
// FPS: per cloud, 16 iterative argmax selections (first = vs MLP keypoints)
// jnp.argmax first-occurrence tie-break preserved (prefer smaller index).
// ----------------------------------------------------------------------------
__global__ __launch_bounds__(1024)
void fps_kernel(const float* __restrict__ src, const float* __restrict__ tgt,
                float* __restrict__ out)
{
    const int slot = blockIdx.x, t = threadIdx.x;
    const float* pts = (slot < 16) ? (src + (size_t)slot*NPTS*3)
                                   : (tgt + (size_t)(slot-16)*NPTS*3);
    float* kout = (slot < 16) ? (out + OUT_DEF + slot*48)
                              : (out + OUT_DEF + OUT_KP + (slot-16)*48);

    __shared__ float skp[48];
    __shared__ float sredV[32];
    __shared__ int   sredI[32];
    __shared__ float selS[3];
    if (t < 48) skp[t] = g_kp[slot*48 + t];

    float px[16], py[16], pz[16], mind[16];
    #pragma unroll
    for (int i = 0; i < 16; i++) {
        int n = t + i*1024;
        px[i] = pts[n*3+0]; py[i] = pts[n*3+1]; pz[i] = pts[n*3+2];
    }
    __syncthreads();

    #pragma unroll
    for (int i = 0; i < 16; i++) {
        float best = 1e30f;
        #pragma unroll
        for (int k = 0; k < 16; k++) {
            float dx = px[i]-skp[k*3+0], dy = py[i]-skp[k*3+1], dz = pz[i]-skp[k*3+2];
            best = fminf(best, dx*dx + dy*dy + dz*dz);
        }
        mind[i] = best;
    }

    for (int it = 0; it < 16; it++) {
        float bv = -1e30f; int bi = 0x7fffffff;
        #pragma unroll
        for (int i = 0; i < 16; i++) {
            if (mind[i] > bv) { bv = mind[i]; bi = t + i*1024; }
        }
        #pragma unroll
        for (int o = 16; o > 0; o >>= 1) {
            float ov = __shfl_down_sync(0xffffffffu, bv, o);
            int   oi = __shfl_down_sync(0xffffffffu, bi, o);
            if (ov > bv || (ov == bv && oi < bi)) { bv = ov; bi = oi; }
        }
        if ((t & 31) == 0) { sredV[t>>5] = bv; sredI[t>>5] = bi; }
        __syncthreads();
        if (t < 32) {
            bv = sredV[t]; bi = sredI[t];
            #pragma unroll
            for (int o = 16; o > 0; o >>= 1) {
                float ov = __shfl_down_sync(0xffffffffu, bv, o);
                int   oi = __shfl_down_sync(0xffffffffu, bi, o);
                if (ov > bv || (ov == bv && oi < bi)) { bv = ov; bi = oi; }
            }
            if (t == 0) {
                float sx = pts[bi*3+0], sy = pts[bi*3+1], sz = pts[bi*3+2];
                selS[0] = sx; selS[1] = sy; selS[2] = sz;
                kout[it*3+0] = sx; kout[it*3+1] = sy; kout[it*3+2] = sz;
                g_sel[slot*48 + it*3+0] = sx;
                g_sel[slot*48 + it*3+1] = sy;
                g_sel[slot*48 + it*3+2] = sz;
            }
        }
        __syncthreads();
        float sx = selS[0], sy = selS[1], sz = selS[2];
        #pragma unroll
        for (int i = 0; i < 16; i++) {
            float dx = px[i]-sx, dy = py[i]-sy, dz = pz[i]-sz;
            float d = dx*dx + dy*dy + dz*dz;
            mind[i] = (it == 0) ? d : fminf(mind[i], d);  // it==0: REPLACE (ref)
        }
    }
}

// ----------------------------------------------------------------------------
// Cage MLP: diff[48] -> relu(128) -> 1536; build cage = grid + disp
// ----------------------------------------------------------------------------
__global__ void cage_kernel(const float* __restrict__ cgw1, const float* __restrict__ cgb1,
                            const float* __restrict__ cgw2, const float* __restrict__ cgb2)
{
    __shared__ float diff[48];
    __shared__ float h[128];
    int b = blockIdx.x, t = threadIdx.x;
    if (t < 48) diff[t] = g_sel[(16+b)*48 + t] - g_sel[b*48 + t];
    __syncthreads();
    float a = cgb1[t];
    for (int k = 0; k < 48; k++) a = fmaf(diff[k], cgw1[t*48+k], a);
    h[t] = fmaxf(a, 0.f);
    __syncthreads();
    for (int o = t; o < 1536; o += 128) {
        float acc = cgb2[o];
        for (int k = 0; k < 128; k++) acc = fmaf(h[k], cgw2[o*128+k], acc);
        int c = o % 3, cell = o / 3;
        int i = cell >> 6, j = (cell >> 3) & 7, kz = cell & 7;
        int li = (c == 0) ? i : (c == 1) ? j : kz;
        g_cage[b*1536 + o] = (float)li * (1.0f/7.0f) + acc;
    }
}

// ----------------------------------------------------------------------------
// Per-batch min/max of source points
// ----------------------------------------------------------------------------
__global__ __launch_bounds__(1024)
void pmm_kernel(const float* __restrict__ src)
{
    int b = blockIdx.x, t = threadIdx.x;
    const float* p = src + (size_t)b*NPTS*3;
    float mn0=1e30f, mn1=1e30f, mn2=1e30f, mx0=-1e30f, mx1=-1e30f, mx2=-1e30f;
    for (int n = t; n < NPTS; n += 1024) {
        float x = p[n*3+0], y = p[n*3+1], z = p[n*3+2];
        mn0 = fminf(mn0,x); mx0 = fmaxf(mx0,x);
        mn1 = fminf(mn1,y); mx1 = fmaxf(mx1,y);
        mn2 = fminf(mn2,z); mx2 = fmaxf(mx2,z);
    }
    #pragma unroll
    for (int o = 16; o > 0; o >>= 1) {
        mn0 = fminf(mn0, __shfl_down_sync(0xffffffffu, mn0, o));
        mn1 = fminf(mn1, __shfl_down_sync(0xffffffffu, mn1, o));
        mn2 = fminf(mn2, __shfl_down_sync(0xffffffffu, mn2, o));
        mx0 = fmaxf(mx0, __shfl_down_sync(0xffffffffu, mx0, o));
        mx1 = fmaxf(mx1, __shfl_down_sync(0xffffffffu, mx1, o));
        mx2 = fmaxf(mx2, __shfl_down_sync(0xffffffffu, mx2, o));
    }
    __shared__ float s[32][6];
    if ((t & 31) == 0) {
        s[t>>5][0]=mn0; s[t>>5][1]=mn1; s[t>>5][2]=mn2;
        s[t>>5][3]=mx0; s[t>>5][4]=mx1; s[t>>5][5]=mx2;
    }
    __syncthreads();
    if (t < 32) {
        mn0=s[t][0]; mn1=s[t][1]; mn2=s[t][2]; mx0=s[t][3]; mx1=s[t][4]; mx2=s[t][5];
        #pragma unroll
        for (int o = 16; o > 0; o >>= 1) {
            mn0 = fminf(mn0, __shfl_down_sync(0xffffffffu, mn0, o));
            mn1 = fminf(mn1, __shfl_down_sync(0xffffffffu, mn1, o));
            mn2 = fminf(mn2, __shfl_down_sync(0xffffffffu, mn2, o));
            mx0 = fmaxf(mx0, __shfl_down_sync(0xffffffffu, mx0, o));
            mx1 = fmaxf(mx1, __shfl_down_sync(0xffffffffu, mx1, o));
            mx2 = fmaxf(mx2, __shfl_down_sync(0xffffffffu, mx2, o));
        }
        if (t == 0) {
            g_pmm[b*6+0]=mn0; g_pmm[b*6+1]=mn1; g_pmm[b*6+2]=mn2;
            g_pmm[b*6+3]=mx0; g_pmm[b*6+4]=mx1; g_pmm[b*6+5]=mx2;
        }
    }
}

// ----------------------------------------------------------------------------
// Trilinear cage deform
// ----------------------------------------------------------------------------
__global__ void deform_kernel(const float* __restrict__ src, float* __restrict__ out)
{
    int b = blockIdx.y, t = threadIdx.x;
    __shared__ float cg[1536];
    __shared__ float pm[6];
    for (int i = t; i < 1536; i += 256) cg[i] = g_cage[b*1536 + i];
    if (t < 6) pm[t] = g_pmm[b*6 + t];
    __syncthreads();

    int n = blockIdx.x*256 + t;
    const float* p = src + ((size_t)b*NPTS + n)*3;
    float x = p[0], y = p[1], z = p[2];
    float tx = (x - pm[0]) / (pm[3]-pm[0] + 1e-6f) * 7.f;
    float ty = (y - pm[1]) / (pm[4]-pm[1] + 1e-6f) * 7.f;
    float tz = (z - pm[2]) / (pm[5]-pm[2] + 1e-6f) * 7.f;
    int u = min(max((int)tx, 0), 6);
    int v = min(max((int)ty, 0), 6);
    int w = min(max((int)tz, 0), 6);
    float wx = tx - (float)u, wy = ty - (float)v, wz = tz - (float)w;
    float ax = 1.f-wx, ay = 1.f-wy, az = 1.f-wz;

    int base = u*64 + v*8 + w;
    const float* c000 = &cg[(base     )*3];
    const float* c100 = &cg[(base + 64)*3];
    const float* c010 = &cg[(base +  8)*3];
    const float* c110 = &cg[(base + 72)*3];
    const float* c001 = &cg[(base +  1)*3];
    const float* c101 = &cg[(base + 65)*3];
    const float* c011 = &cg[(base +  9)*3];
    const float* c111 = &cg[(base + 73)*3];

    float w000 = ax*ay*az, w100 = wx*ay*az, w010 = ax*wy*az, w110 = wx*wy*az;
    float w001 = ax*ay*wz, w101 = wx*ay*wz, w011 = ax*wy*wz, w111 = wx*wy*wz;

    #pragma unroll
    for (int c = 0; c < 3; c++) {
        float d = w000*c000[c] + w100*c100[c] + w010*c010[c] + w110*c110[c]
                + w001*c001[c] + w101*c101[c] + w011*c011[c] + w111*c111[c];
        out[((size_t)b*NPTS + n)*3 + c] = p[c] + d;
    }
}

// ----------------------------------------------------------------------------
// Launch
// ----------------------------------------------------------------------------
extern "C" void kernel_launch(void* const* d_in, const int* in_sizes, int n_in,
                              void* d_out, int out_size)
{
    const float* src  = (const float*)d_in[0];
    const float* tgt  = (const float*)d_in[1];
    const float* ew1  = (const float*)d_in[2];
    const float* eb1  = (const float*)d_in[3];
    const float* g1   = (const float*)d_in[4];
    const float* be1  = (const float*)d_in[5];
    const float* m1   = (const float*)d_in[6];
    const float* v1   = (const float*)d_in[7];
    const float* ew2  = (const float*)d_in[8];
    const float* eb2  = (const float*)d_in[9];
    const float* g2   = (const float*)d_in[10];
    const float* be2  = (const float*)d_in[11];
    const float* m2   = (const float*)d_in[12];
    const float* v2   = (const float*)d_in[13];
    const float* ew3  = (const float*)d_in[14];
    const float* eb3  = (const float*)d_in[15];
    const float* g3   = (const float*)d_in[16];
    const float* be3  = (const float*)d_in[17];
    const float* m3   = (const float*)d_in[18];
    const float* v3   = (const float*)d_in[19];
    const float* kpw1 = (const float*)d_in[20];
    const float* kpb1 = (const float*)d_in[21];
    const float* kpw2 = (const float*)d_in[22];
    const float* kpb2 = (const float*)d_in[23];
    const float* cgw1 = (const float*)d_in[24];
    const float* cgb1 = (const float*)d_in[25];
    const float* cgw2 = (const float*)d_in[26];
    const float* cgb2 = (const float*)d_in[27];
    float* out = (float*)d_out;

    cudaFuncSetAttribute(enc_kernel, cudaFuncAttributeMaxDynamicSharedMemorySize,
                         ENC_SMEM_BYTES);

    prep_kernel<<<1, 256>>>(ew1, eb1, g1, be1, m1, v1,
                            ew2, eb2, g2, be2, m2, v2,
                            ew3, eb3, g3, be3, m3, v3);
    enc_kernel<<<dim3(NPTS/(ENC_TP*ENC_SUBT), NSLOT), 256, ENC_SMEM_BYTES>>>(src, tgt);
    kp_kernel<<<NSLOT, 128>>>(kpw1, kpb1, kpw2, kpb2);
    fps_kernel<<<NSLOT, 1024>>>(src, tgt, out);
    cage_kernel<<<NB, 128>>>(cgw1, cgb1, cgw2, cgb2);
    pmm_kernel<<<NB, 1024>>>(src);
    deform_kernel<<<dim3(NPTS/256, NB), 256>>>(src, out);
}